// round 14
// baseline (speedup 1.0000x reference)
#include <cuda_runtime.h>
#include <cuda_fp16.h>
#include <cstdint>

#define D_MODEL 1024
#define NUM_HEADS 16
#define DK 64
#define BATCH 4
#define SEQ 2048
#define MROWS (BATCH * SEQ)   /* 8192 */
#define KVTILES (SEQ / 128)   /* 16 */

// ---------------- scratch (all single fp16) ----------------
__device__ __half g_Q16[BATCH * NUM_HEADS * SEQ * DK];
__device__ __half g_K16[BATCH * NUM_HEADS * SEQ * DK];
__device__ __half g_V16[BATCH * NUM_HEADS * SEQ * DK];
__device__ __half g_ctx16[MROWS * D_MODEL];
__device__ __half g_a16[3 * MROWS * D_MODEL];     // query,key,value acts
__device__ __half g_w16[4 * D_MODEL * D_MODEL];   // Wq,Wk,Wv,Wo

// ---------------- helpers ----------------
__device__ __forceinline__ uint32_t smem_u32(const void* p) {
    uint32_t a;
    asm("{ .reg .u64 t; cvta.to.shared.u64 t, %1; cvt.u32.u64 %0, t; }" : "=r"(a) : "l"(p));
    return a;
}
#define CP_ASYNC16(saddr, gptr) \
    asm volatile("cp.async.cg.shared.global [%0], [%1], 16;" :: "r"((uint32_t)(saddr)), "l"(gptr))
#define CP_ASYNC_COMMIT()    asm volatile("cp.async.commit_group;" ::: "memory")
#define CP_ASYNC_WAIT_ALL()  asm volatile("cp.async.wait_group 0;" ::: "memory")
#define CP_ASYNC_WAIT_1()    asm volatile("cp.async.wait_group 1;" ::: "memory")

__device__ __forceinline__ void ldsm4(uint32_t r[4], uint32_t a) {
    asm volatile("ldmatrix.sync.aligned.m8n8.x4.shared.b16 {%0,%1,%2,%3}, [%4];"
        : "=r"(r[0]), "=r"(r[1]), "=r"(r[2]), "=r"(r[3]) : "r"(a));
}
__device__ __forceinline__ void ldsm4t(uint32_t r[4], uint32_t a) {
    asm volatile("ldmatrix.sync.aligned.m8n8.x4.trans.shared.b16 {%0,%1,%2,%3}, [%4];"
        : "=r"(r[0]), "=r"(r[1]), "=r"(r[2]), "=r"(r[3]) : "r"(a));
}
__device__ __forceinline__ void mma_f16(float c[4], const uint32_t a[4], uint32_t b0, uint32_t b1) {
    asm volatile("mma.sync.aligned.m16n8k16.row.col.f32.f16.f16.f32 "
        "{%0,%1,%2,%3}, {%4,%5,%6,%7}, {%8,%9}, {%0,%1,%2,%3};"
        : "+f"(c[0]), "+f"(c[1]), "+f"(c[2]), "+f"(c[3])
        : "r"(a[0]), "r"(a[1]), "r"(a[2]), "r"(a[3]), "r"(b0), "r"(b1));
}
__device__ __forceinline__ uint32_t pack_h16(float x, float y) {
    __half2 h = __floats2half2_rn(x, y);
    return *(uint32_t*)&h;
}

// ============================================================================
// conversions (single fp16 only) — R12 structure
// ============================================================================
__global__ __launch_bounds__(256) void conv_w4(
    const float* __restrict__ x0, const float* __restrict__ x1,
    const float* __restrict__ x2, const float* __restrict__ x3,
    __half* __restrict__ h16, int n4)
{
    int i = blockIdx.x * blockDim.x + threadIdx.x;
    if (i >= n4) return;
    const float* x = (blockIdx.y == 0) ? x0 : (blockIdx.y == 1) ? x1
                   : (blockIdx.y == 2) ? x2 : x3;
    size_t o = (size_t)blockIdx.y * n4 + i;
    float4 v = ((const float4*)x)[i];
    uint2 H;
    H.x = pack_h16(v.x, v.y); H.y = pack_h16(v.z, v.w);
    ((uint2*)h16)[o] = H;
}
__global__ __launch_bounds__(256) void conv_a3(
    const float* __restrict__ x0, const float* __restrict__ x1,
    const float* __restrict__ x2, __half* __restrict__ h16, int n4)
{
    int i = blockIdx.x * blockDim.x + threadIdx.x;
    if (i >= n4) return;
    const float* x = (blockIdx.y == 0) ? x0 : (blockIdx.y == 1) ? x1 : x2;
    size_t o = (size_t)blockIdx.y * n4 + i;
    float4 v = ((const float4*)x)[i];
    uint2 H;
    H.x = pack_h16(v.x, v.y); H.y = pack_h16(v.z, v.w);
    ((uint2*)h16)[o] = H;
}

// ============================================================================
// fp16 1-term GEMM. BM=BN=128, BK=64, 8 warps, 3-stage cp.async pipeline.
// ============================================================================
#define BK 64
#define GST 144
#define MAT16 (128 * GST)
#define STG16 (2 * MAT16)
#define NIT (D_MODEL / BK)
#define NSTG 3
#define GEMM16_SMEM (NSTG * STG16)

__device__ __forceinline__ void gemm16_main(
    uint32_t sb, int t,
    const __half* __restrict__ A, const __half* __restrict__ W,
    int m0, int n0, float c[4][4][4])
{
    const int lane = t & 31, wid = t >> 5;
    const int wm = wid >> 2, wn = wid & 3;

    auto load_stage = [&](int s, int it) {
        const int k0 = it * BK;
        const uint32_t st = sb + s * STG16;
#pragma unroll
        for (int j = 0; j < 4; j++) {
            int idx = t + j * 256;
            int r = idx >> 3, cc = idx & 7;
            uint32_t so = (uint32_t)(r * GST + cc * 16);
            CP_ASYNC16(st + 0 * MAT16 + so, A + (size_t)(m0 + r) * D_MODEL + k0 + cc * 8);
            CP_ASYNC16(st + 1 * MAT16 + so, W + (size_t)(n0 + r) * D_MODEL + k0 + cc * 8);
        }
    };

    load_stage(0, 0);
    CP_ASYNC_COMMIT();
    load_stage(1, 1);
    CP_ASYNC_COMMIT();

    for (int it = 0; it < NIT; ++it) {
        const int s = it % NSTG;
        CP_ASYNC_WAIT_1();
        __syncthreads();
        if (it + 2 < NIT) {
            load_stage((it + 2) % NSTG, it + 2);
            CP_ASYNC_COMMIT();
        }
        const uint32_t st = sb + s * STG16;
#pragma unroll
        for (int kk = 0; kk < 4; kk++) {
            uint32_t ah[4][4];
#pragma unroll
            for (int mi = 0; mi < 4; mi++) {
                uint32_t ro = (uint32_t)((wm * 64 + mi * 16 + (lane & 15)) * GST
                                         + (kk * 16 + (lane >> 4) * 8) * 2);
                ldsm4(ah[mi], st + 0 * MAT16 + ro);
            }
            uint32_t bh_[2][4];
#pragma unroll
            for (int nj = 0; nj < 2; nj++) {
                uint32_t ro = (uint32_t)((wn * 32 + nj * 16 + (lane & 7) + ((lane >> 4) * 8)) * GST
                                         + (kk * 16 + ((lane >> 3) & 1) * 8) * 2);
                ldsm4(bh_[nj], st + 1 * MAT16 + ro);
            }
#pragma unroll
            for (int mi = 0; mi < 4; mi++)
#pragma unroll
                for (int ni = 0; ni < 4; ni++) {
                    const int nj = ni >> 1, ss = (ni & 1) * 2;
                    mma_f16(c[mi][ni], ah[mi], bh_[nj][ss], bh_[nj][ss + 1]);
                }
        }
    }
}

// ---- fused Q/K/V projections (Q scaled by 0.125*log2e for exp2 softmax) ----
__global__ __launch_bounds__(256, 2) void gemm_qkv16(
    const __half* __restrict__ a16, const __half* __restrict__ w16,
    const float* __restrict__ bq, const float* __restrict__ bk,
    const float* __restrict__ bv,
    __half* __restrict__ q16, __half* __restrict__ k16, __half* __restrict__ v16)
{
    extern __shared__ char smem[];
    const uint32_t sb = smem_u32(smem);
    const int t = threadIdx.x;
    const int lane = t & 31, wid = t >> 5;
    const int wm = wid >> 2, wn = wid & 3;
    const int m0 = blockIdx.y * 128, n0 = blockIdx.x * 128;
    const int z = blockIdx.z;

    const __half* A = a16 + (size_t)z * MROWS * D_MODEL;
    const __half* W = w16 + (size_t)z * D_MODEL * D_MODEL;
    const float* bias = (z == 0) ? bq : (z == 1) ? bk : bv;
    __half* C = (z == 0) ? q16 : (z == 1) ? k16 : v16;
    const float oscale = (z == 0) ? 0.125f * 1.44269504088896f : 1.0f;

    float c[4][4][4];
#pragma unroll
    for (int i = 0; i < 4; i++)
#pragma unroll
        for (int j = 0; j < 4; j++)
#pragma unroll
            for (int k = 0; k < 4; k++) c[i][j][k] = 0.0f;

    gemm16_main(sb, t, A, W, m0, n0, c);

#pragma unroll
    for (int mi = 0; mi < 4; mi++) {
        const int r0 = m0 + wm * 64 + mi * 16 + (lane >> 2);
#pragma unroll
        for (int ni = 0; ni < 4; ni++) {
            const int col = n0 + wn * 32 + ni * 8 + (lane & 3) * 2;
            const float b0 = bias[col], b1 = bias[col + 1];
            const int h = col >> 6, d = col & 63;
            float v00 = (c[mi][ni][0] + b0) * oscale, v01 = (c[mi][ni][1] + b1) * oscale;
            float v10 = (c[mi][ni][2] + b0) * oscale, v11 = (c[mi][ni][3] + b1) * oscale;
#pragma unroll
            for (int rr = 0; rr < 2; rr++) {
                const int m = r0 + rr * 8;
                const int b = m >> 11, sdx = m & 2047;
                const size_t off = (((size_t)(b * NUM_HEADS + h) * SEQ + sdx) * DK + d);
                *(uint32_t*)(C + off) = pack_h16(rr ? v10 : v00, rr ? v11 : v01);
            }
        }
    }
}

// ---- output projection: fp32 row-major out ----
__global__ __launch_bounds__(256, 2) void gemm_out16(
    const __half* __restrict__ A, const __half* __restrict__ W,
    const float* __restrict__ bias, float* __restrict__ Cf)
{
    extern __shared__ char smem[];
    const uint32_t sb = smem_u32(smem);
    const int t = threadIdx.x;
    const int lane = t & 31, wid = t >> 5;
    const int wm = wid >> 2, wn = wid & 3;
    const int m0 = blockIdx.y * 128, n0 = blockIdx.x * 128;

    float c[4][4][4];
#pragma unroll
    for (int i = 0; i < 4; i++)
#pragma unroll
        for (int j = 0; j < 4; j++)
#pragma unroll
            for (int k = 0; k < 4; k++) c[i][j][k] = 0.0f;

    gemm16_main(sb, t, A, W, m0, n0, c);

#pragma unroll
    for (int mi = 0; mi < 4; mi++) {
        const int r0 = m0 + wm * 64 + mi * 16 + (lane >> 2);
#pragma unroll
        for (int ni = 0; ni < 4; ni++) {
            const int col = n0 + wn * 32 + ni * 8 + (lane & 3) * 2;
            const float b0 = bias[col], b1 = bias[col + 1];
            *(float2*)(Cf + (size_t)r0 * D_MODEL + col) =
                make_float2(c[mi][ni][0] + b0, c[mi][ni][1] + b1);
            *(float2*)(Cf + (size_t)(r0 + 8) * D_MODEL + col) =
                make_float2(c[mi][ni][2] + b0, c[mi][ni][3] + b1);
        }
    }
}

// ============================================================================
// FA2 attention: R12 structure (exp-all-then-PV) + deferred l-reduction only.
// 256 threads / 8 warps / 128 q-rows, 2 CTAs/SM. exp2-domain softmax.
// ============================================================================
#define AST 144
#define AT_Q  0
#define AT_K(b) (AT_Q + 128 * AST + (b) * (128 * AST))
#define AT_V(b) (AT_Q + 128 * AST + 2 * (128 * AST) + (b) * (128 * AST))
#define ATTN_SMEM (128 * AST + 4 * (128 * AST))   /* 92160 B */

__global__ __launch_bounds__(256, 2) void attn_tc()
{
    extern __shared__ char smem[];
    const uint32_t sb = smem_u32(smem);
    const int t = threadIdx.x;
    const int lane = t & 31, w = t >> 5;
    const int qt = blockIdx.x, bh = blockIdx.y;

    const __half* Qs = g_Q16 + ((size_t)bh * SEQ + qt * 128) * DK;
    const __half* Kg = g_K16 + (size_t)bh * SEQ * DK;
    const __half* Vg = g_V16 + (size_t)bh * SEQ * DK;

    auto ldtile = [&](uint32_t dstoff, const __half* src) {   // 128x64 fp16
#pragma unroll
        for (int j = 0; j < 4; j++) {
            int idx = t + j * 256;
            int r = idx >> 3, cc = idx & 7;
            CP_ASYNC16(sb + dstoff + r * AST + cc * 16, src + r * DK + cc * 8);
        }
    };

    ldtile(AT_Q, Qs);
    ldtile(AT_K(0), Kg);
    ldtile(AT_V(0), Vg);
    CP_ASYNC_COMMIT();
    CP_ASYNC_WAIT_ALL();
    __syncthreads();

    float o[8][4];
#pragma unroll
    for (int i = 0; i < 8; i++)
#pragma unroll
        for (int k = 0; k < 4; k++) o[i][k] = 0.0f;
    float m0 = -1e30f, m1 = -1e30f;
    float ls0 = 0.0f, ls1 = 0.0f;    // per-lane partial l, quad-reduced at end

    for (int kt = 0; kt < KVTILES; kt++) {
        const int vb = kt & 1;

        if (kt + 1 < KVTILES) {
            ldtile(AT_K(vb ^ 1), Kg + (size_t)(kt + 1) * 128 * DK);
            ldtile(AT_V(vb ^ 1), Vg + (size_t)(kt + 1) * 128 * DK);
            CP_ASYNC_COMMIT();
        }

        // ---- S' = Q' K^T  (log2 units) ----
        float c[16][4];
#pragma unroll
        for (int i = 0; i < 16; i++)
#pragma unroll
            for (int k = 0; k < 4; k++) c[i][k] = 0.0f;

#pragma unroll
        for (int kk = 0; kk < 4; kk++) {
            uint32_t q[4];
            {
                uint32_t ro = (uint32_t)((w * 16 + (lane & 15)) * AST
                                         + (kk * 16 + (lane >> 4) * 8) * 2);
                ldsm4(q, sb + AT_Q + ro);
            }
#pragma unroll
            for (int nj = 0; nj < 8; nj++) {
                uint32_t bk_[4];
                uint32_t ro = (uint32_t)((nj * 16 + (lane & 7) + ((lane >> 4) * 8)) * AST
                                         + (kk * 16 + ((lane >> 3) & 1) * 8) * 2);
                ldsm4(bk_, sb + AT_K(vb) + ro);
                mma_f16(c[2 * nj],     q, bk_[0], bk_[1]);
                mma_f16(c[2 * nj + 1], q, bk_[2], bk_[3]);
            }
        }

        // ---- warp-local online softmax (exp2 domain) ----
        float mx0 = -1e30f, mx1 = -1e30f;
#pragma unroll
        for (int ni = 0; ni < 16; ni++) {
            mx0 = fmaxf(mx0, fmaxf(c[ni][0], c[ni][1]));
            mx1 = fmaxf(mx1, fmaxf(c[ni][2], c[ni][3]));
        }
        mx0 = fmaxf(mx0, __shfl_xor_sync(0xffffffffu, mx0, 1));
        mx0 = fmaxf(mx0, __shfl_xor_sync(0xffffffffu, mx0, 2));
        mx1 = fmaxf(mx1, __shfl_xor_sync(0xffffffffu, mx1, 1));
        mx1 = fmaxf(mx1, __shfl_xor_sync(0xffffffffu, mx1, 2));

        const float nm0 = fmaxf(m0, mx0), nm1 = fmaxf(m1, mx1);
        const float alpha0 = exp2f(m0 - nm0), alpha1 = exp2f(m1 - nm1);
        m0 = nm0; m1 = nm1;

        float s0 = 0.0f, s1 = 0.0f;
#pragma unroll
        for (int ni = 0; ni < 16; ni++) {
            c[ni][0] = exp2f(c[ni][0] - nm0);
            c[ni][1] = exp2f(c[ni][1] - nm0);
            c[ni][2] = exp2f(c[ni][2] - nm1);
            c[ni][3] = exp2f(c[ni][3] - nm1);
            s0 += c[ni][0] + c[ni][1];
            s1 += c[ni][2] + c[ni][3];
        }
        // deferred l: per-lane partials only (no shuffles in the loop)
        ls0 = ls0 * alpha0 + s0;
        ls1 = ls1 * alpha1 + s1;

#pragma unroll
        for (int i = 0; i < 8; i++) {
            o[i][0] *= alpha0; o[i][1] *= alpha0;
            o[i][2] *= alpha1; o[i][3] *= alpha1;
        }

        // ---- O += P V ----
#pragma unroll
        for (int kk = 0; kk < 8; kk++) {
            uint32_t ph[4];
            ph[0] = pack_h16(c[2 * kk][0], c[2 * kk][1]);
            ph[1] = pack_h16(c[2 * kk][2], c[2 * kk][3]);
            ph[2] = pack_h16(c[2 * kk + 1][0], c[2 * kk + 1][1]);
            ph[3] = pack_h16(c[2 * kk + 1][2], c[2 * kk + 1][3]);
#pragma unroll
            for (int nj = 0; nj < 4; nj++) {
                uint32_t vh[4];
                uint32_t ro = (uint32_t)((kk * 16 + (lane & 15)) * AST
                                         + (nj * 16 + (lane >> 4) * 8) * 2);
                ldsm4t(vh, sb + AT_V(vb) + ro);
                mma_f16(o[2 * nj],     ph, vh[0], vh[1]);
                mma_f16(o[2 * nj + 1], ph, vh[2], vh[3]);
            }
        }

        if (kt + 1 < KVTILES) CP_ASYNC_WAIT_ALL();
        __syncthreads();
    }

    // ---- epilogue: quad-reduce l, normalize, emit fp16 ctx ----
    ls0 += __shfl_xor_sync(0xffffffffu, ls0, 1);
    ls0 += __shfl_xor_sync(0xffffffffu, ls0, 2);
    ls1 += __shfl_xor_sync(0xffffffffu, ls1, 1);
    ls1 += __shfl_xor_sync(0xffffffffu, ls1, 2);

    const int b = bh >> 4, h = bh & 15;
    const float inv0 = 1.0f / ls0, inv1 = 1.0f / ls1;
    const size_t row0 = (size_t)(b * SEQ + qt * 128 + w * 16 + (lane >> 2));
#pragma unroll
    for (int on = 0; on < 8; on++) {
        const int colg = h * DK + on * 8 + (lane & 3) * 2;
        *(uint32_t*)(g_ctx16 + row0 * D_MODEL + colg) = pack_h16(o[on][0] * inv0, o[on][1] * inv0);
        *(uint32_t*)(g_ctx16 + (row0 + 8) * D_MODEL + colg) = pack_h16(o[on][2] * inv1, o[on][3] * inv1);
    }
}

// ============================================================================
// launch
// ============================================================================
extern "C" void kernel_launch(void* const* d_in, const int* in_sizes, int n_in,
                              void* d_out, int out_size)
{
    const float* query  = (const float*)d_in[0];
    const float* key_in = (const float*)d_in[1];
    const float* value  = (const float*)d_in[2];
    const float* Wq = (const float*)d_in[3];
    const float* bq = (const float*)d_in[4];
    const float* Wk = (const float*)d_in[5];
    const float* bk = (const float*)d_in[6];
    const float* Wv = (const float*)d_in[7];
    const float* bv = (const float*)d_in[8];
    const float* Wo = (const float*)d_in[9];
    const float* bo = (const float*)d_in[10];
    float* out = (float*)d_out;

    __half *q16, *k16, *v16, *ctx16, *a16, *w16;
    cudaGetSymbolAddress((void**)&q16, g_Q16);
    cudaGetSymbolAddress((void**)&k16, g_K16);
    cudaGetSymbolAddress((void**)&v16, g_V16);
    cudaGetSymbolAddress((void**)&ctx16, g_ctx16);
    cudaGetSymbolAddress((void**)&a16, g_a16);
    cudaGetSymbolAddress((void**)&w16, g_w16);

    cudaFuncSetAttribute(gemm_qkv16, cudaFuncAttributeMaxDynamicSharedMemorySize, GEMM16_SMEM);
    cudaFuncSetAttribute(gemm_out16, cudaFuncAttributeMaxDynamicSharedMemorySize, GEMM16_SMEM);
    cudaFuncSetAttribute(attn_tc, cudaFuncAttributeMaxDynamicSharedMemorySize, ATTN_SMEM);

    const int ACT4 = MROWS * D_MODEL / 4;
    const int W4   = D_MODEL * D_MODEL / 4;
    const size_t WSL = (size_t)D_MODEL * D_MODEL;

    conv_w4<<<dim3((W4 + 255) / 256, 4), 256>>>(Wq, Wk, Wv, Wo, w16, W4);
    conv_a3<<<dim3((ACT4 + 255) / 256, 3), 256>>>(query, key_in, value, a16, ACT4);

    gemm_qkv16<<<dim3(D_MODEL / 128, MROWS / 128, 3), 256, GEMM16_SMEM>>>(
        a16, w16, bq, bk, bv, q16, k16, v16);

    attn_tc<<<dim3(SEQ / 128, BATCH * NUM_HEADS), dim3(256), ATTN_SMEM>>>();

    gemm_out16<<<dim3(D_MODEL / 128, MROWS / 128), 256, GEMM16_SMEM>>>(
        ctx16, w16 + 3 * WSL, bo, out);
}

// round 15
// speedup vs baseline: 1.0438x; 1.0438x over previous
#include <cuda_runtime.h>
#include <cuda_fp16.h>
#include <cstdint>

#define D_MODEL 1024
#define NUM_HEADS 16
#define DK 64
#define BATCH 4
#define SEQ 2048
#define MROWS (BATCH * SEQ)   /* 8192 */
#define KVTILES (SEQ / 128)   /* 16 */

// ---------------- scratch (all single fp16) ----------------
__device__ __half g_Q16[BATCH * NUM_HEADS * SEQ * DK];
__device__ __half g_K16[BATCH * NUM_HEADS * SEQ * DK];
__device__ __half g_V16[BATCH * NUM_HEADS * SEQ * DK];
__device__ __half g_ctx16[MROWS * D_MODEL];
__device__ __half g_a16[3 * MROWS * D_MODEL];     // query,key,value acts
__device__ __half g_w16[4 * D_MODEL * D_MODEL];   // Wq,Wk,Wv,Wo

// ---------------- helpers ----------------
__device__ __forceinline__ uint32_t smem_u32(const void* p) {
    uint32_t a;
    asm("{ .reg .u64 t; cvta.to.shared.u64 t, %1; cvt.u32.u64 %0, t; }" : "=r"(a) : "l"(p));
    return a;
}
#define CP_ASYNC16(saddr, gptr) \
    asm volatile("cp.async.cg.shared.global [%0], [%1], 16;" :: "r"((uint32_t)(saddr)), "l"(gptr))
#define CP_ASYNC_COMMIT()    asm volatile("cp.async.commit_group;" ::: "memory")
#define CP_ASYNC_WAIT_ALL()  asm volatile("cp.async.wait_group 0;" ::: "memory")
#define CP_ASYNC_WAIT_1()    asm volatile("cp.async.wait_group 1;" ::: "memory")

__device__ __forceinline__ void ldsm4(uint32_t r[4], uint32_t a) {
    asm volatile("ldmatrix.sync.aligned.m8n8.x4.shared.b16 {%0,%1,%2,%3}, [%4];"
        : "=r"(r[0]), "=r"(r[1]), "=r"(r[2]), "=r"(r[3]) : "r"(a));
}
__device__ __forceinline__ void ldsm4t(uint32_t r[4], uint32_t a) {
    asm volatile("ldmatrix.sync.aligned.m8n8.x4.trans.shared.b16 {%0,%1,%2,%3}, [%4];"
        : "=r"(r[0]), "=r"(r[1]), "=r"(r[2]), "=r"(r[3]) : "r"(a));
}
__device__ __forceinline__ void mma_f16(float c[4], const uint32_t a[4], uint32_t b0, uint32_t b1) {
    asm volatile("mma.sync.aligned.m16n8k16.row.col.f32.f16.f16.f32 "
        "{%0,%1,%2,%3}, {%4,%5,%6,%7}, {%8,%9}, {%0,%1,%2,%3};"
        : "+f"(c[0]), "+f"(c[1]), "+f"(c[2]), "+f"(c[3])
        : "r"(a[0]), "r"(a[1]), "r"(a[2]), "r"(a[3]), "r"(b0), "r"(b1));
}
__device__ __forceinline__ uint32_t pack_h16(float x, float y) {
    __half2 h = __floats2half2_rn(x, y);
    return *(uint32_t*)&h;
}

// ============================================================================
// conversions: 4 float4 per thread (MLP=4, DRAM-saturating). Math per element
// identical to previous rounds -> bit-identical outputs.
// ============================================================================
__global__ __launch_bounds__(256) void conv_w4(
    const float* __restrict__ x0, const float* __restrict__ x1,
    const float* __restrict__ x2, const float* __restrict__ x3,
    __half* __restrict__ h16, int n4)
{
    int i0 = (blockIdx.x * blockDim.x + threadIdx.x) * 4;
    if (i0 >= n4) return;
    const float* x = (blockIdx.y == 0) ? x0 : (blockIdx.y == 1) ? x1
                   : (blockIdx.y == 2) ? x2 : x3;
    size_t base = (size_t)blockIdx.y * n4;
    float4 v0 = ((const float4*)x)[i0 + 0];
    float4 v1 = ((const float4*)x)[i0 + 1];
    float4 v2 = ((const float4*)x)[i0 + 2];
    float4 v3 = ((const float4*)x)[i0 + 3];
    uint4 H0, H1;
    H0.x = pack_h16(v0.x, v0.y); H0.y = pack_h16(v0.z, v0.w);
    H0.z = pack_h16(v1.x, v1.y); H0.w = pack_h16(v1.z, v1.w);
    H1.x = pack_h16(v2.x, v2.y); H1.y = pack_h16(v2.z, v2.w);
    H1.z = pack_h16(v3.x, v3.y); H1.w = pack_h16(v3.z, v3.w);
    uint2* dst = (uint2*)(h16 + base * 4) + i0;
    *(uint4*)(dst + 0) = H0;
    *(uint4*)(dst + 2) = H1;
}
__global__ __launch_bounds__(256) void conv_a3(
    const float* __restrict__ x0, const float* __restrict__ x1,
    const float* __restrict__ x2, __half* __restrict__ h16, int n4)
{
    int i0 = (blockIdx.x * blockDim.x + threadIdx.x) * 4;
    if (i0 >= n4) return;
    const float* x = (blockIdx.y == 0) ? x0 : (blockIdx.y == 1) ? x1 : x2;
    size_t base = (size_t)blockIdx.y * n4;
    float4 v0 = ((const float4*)x)[i0 + 0];
    float4 v1 = ((const float4*)x)[i0 + 1];
    float4 v2 = ((const float4*)x)[i0 + 2];
    float4 v3 = ((const float4*)x)[i0 + 3];
    uint4 H0, H1;
    H0.x = pack_h16(v0.x, v0.y); H0.y = pack_h16(v0.z, v0.w);
    H0.z = pack_h16(v1.x, v1.y); H0.w = pack_h16(v1.z, v1.w);
    H1.x = pack_h16(v2.x, v2.y); H1.y = pack_h16(v2.z, v2.w);
    H1.z = pack_h16(v3.x, v3.y); H1.w = pack_h16(v3.z, v3.w);
    uint2* dst = (uint2*)(h16 + base * 4) + i0;
    *(uint4*)(dst + 0) = H0;
    *(uint4*)(dst + 2) = H1;
}

// ============================================================================
// fp16 1-term GEMM. BM=BN=128, BK=64, 8 warps, 3-stage cp.async pipeline.
// (unchanged from R12)
// ============================================================================
#define BK 64
#define GST 144
#define MAT16 (128 * GST)
#define STG16 (2 * MAT16)
#define NIT (D_MODEL / BK)
#define NSTG 3
#define GEMM16_SMEM (NSTG * STG16)

__device__ __forceinline__ void gemm16_main(
    uint32_t sb, int t,
    const __half* __restrict__ A, const __half* __restrict__ W,
    int m0, int n0, float c[4][4][4])
{
    const int lane = t & 31, wid = t >> 5;
    const int wm = wid >> 2, wn = wid & 3;

    auto load_stage = [&](int s, int it) {
        const int k0 = it * BK;
        const uint32_t st = sb + s * STG16;
#pragma unroll
        for (int j = 0; j < 4; j++) {
            int idx = t + j * 256;
            int r = idx >> 3, cc = idx & 7;
            uint32_t so = (uint32_t)(r * GST + cc * 16);
            CP_ASYNC16(st + 0 * MAT16 + so, A + (size_t)(m0 + r) * D_MODEL + k0 + cc * 8);
            CP_ASYNC16(st + 1 * MAT16 + so, W + (size_t)(n0 + r) * D_MODEL + k0 + cc * 8);
        }
    };

    load_stage(0, 0);
    CP_ASYNC_COMMIT();
    load_stage(1, 1);
    CP_ASYNC_COMMIT();

    for (int it = 0; it < NIT; ++it) {
        const int s = it % NSTG;
        CP_ASYNC_WAIT_1();
        __syncthreads();
        if (it + 2 < NIT) {
            load_stage((it + 2) % NSTG, it + 2);
            CP_ASYNC_COMMIT();
        }
        const uint32_t st = sb + s * STG16;
#pragma unroll
        for (int kk = 0; kk < 4; kk++) {
            uint32_t ah[4][4];
#pragma unroll
            for (int mi = 0; mi < 4; mi++) {
                uint32_t ro = (uint32_t)((wm * 64 + mi * 16 + (lane & 15)) * GST
                                         + (kk * 16 + (lane >> 4) * 8) * 2);
                ldsm4(ah[mi], st + 0 * MAT16 + ro);
            }
            uint32_t bh_[2][4];
#pragma unroll
            for (int nj = 0; nj < 2; nj++) {
                uint32_t ro = (uint32_t)((wn * 32 + nj * 16 + (lane & 7) + ((lane >> 4) * 8)) * GST
                                         + (kk * 16 + ((lane >> 3) & 1) * 8) * 2);
                ldsm4(bh_[nj], st + 1 * MAT16 + ro);
            }
#pragma unroll
            for (int mi = 0; mi < 4; mi++)
#pragma unroll
                for (int ni = 0; ni < 4; ni++) {
                    const int nj = ni >> 1, ss = (ni & 1) * 2;
                    mma_f16(c[mi][ni], ah[mi], bh_[nj][ss], bh_[nj][ss + 1]);
                }
        }
    }
}

// ---- fused Q/K/V projections (Q scaled by 0.125*log2e for exp2 softmax) ----
__global__ __launch_bounds__(256, 2) void gemm_qkv16(
    const __half* __restrict__ a16, const __half* __restrict__ w16,
    const float* __restrict__ bq, const float* __restrict__ bk,
    const float* __restrict__ bv,
    __half* __restrict__ q16, __half* __restrict__ k16, __half* __restrict__ v16)
{
    extern __shared__ char smem[];
    const uint32_t sb = smem_u32(smem);
    const int t = threadIdx.x;
    const int lane = t & 31, wid = t >> 5;
    const int wm = wid >> 2, wn = wid & 3;
    const int m0 = blockIdx.y * 128, n0 = blockIdx.x * 128;
    const int z = blockIdx.z;

    const __half* A = a16 + (size_t)z * MROWS * D_MODEL;
    const __half* W = w16 + (size_t)z * D_MODEL * D_MODEL;
    const float* bias = (z == 0) ? bq : (z == 1) ? bk : bv;
    __half* C = (z == 0) ? q16 : (z == 1) ? k16 : v16;
    const float oscale = (z == 0) ? 0.125f * 1.44269504088896f : 1.0f;

    float c[4][4][4];
#pragma unroll
    for (int i = 0; i < 4; i++)
#pragma unroll
        for (int j = 0; j < 4; j++)
#pragma unroll
            for (int k = 0; k < 4; k++) c[i][j][k] = 0.0f;

    gemm16_main(sb, t, A, W, m0, n0, c);

#pragma unroll
    for (int mi = 0; mi < 4; mi++) {
        const int r0 = m0 + wm * 64 + mi * 16 + (lane >> 2);
#pragma unroll
        for (int ni = 0; ni < 4; ni++) {
            const int col = n0 + wn * 32 + ni * 8 + (lane & 3) * 2;
            const float b0 = bias[col], b1 = bias[col + 1];
            const int h = col >> 6, d = col & 63;
            float v00 = (c[mi][ni][0] + b0) * oscale, v01 = (c[mi][ni][1] + b1) * oscale;
            float v10 = (c[mi][ni][2] + b0) * oscale, v11 = (c[mi][ni][3] + b1) * oscale;
#pragma unroll
            for (int rr = 0; rr < 2; rr++) {
                const int m = r0 + rr * 8;
                const int b = m >> 11, sdx = m & 2047;
                const size_t off = (((size_t)(b * NUM_HEADS + h) * SEQ + sdx) * DK + d);
                *(uint32_t*)(C + off) = pack_h16(rr ? v10 : v00, rr ? v11 : v01);
            }
        }
    }
}

// ---- output projection: fp32 row-major out ----
__global__ __launch_bounds__(256, 2) void gemm_out16(
    const __half* __restrict__ A, const __half* __restrict__ W,
    const float* __restrict__ bias, float* __restrict__ Cf)
{
    extern __shared__ char smem[];
    const uint32_t sb = smem_u32(smem);
    const int t = threadIdx.x;
    const int lane = t & 31, wid = t >> 5;
    const int wm = wid >> 2, wn = wid & 3;
    const int m0 = blockIdx.y * 128, n0 = blockIdx.x * 128;

    float c[4][4][4];
#pragma unroll
    for (int i = 0; i < 4; i++)
#pragma unroll
        for (int j = 0; j < 4; j++)
#pragma unroll
            for (int k = 0; k < 4; k++) c[i][j][k] = 0.0f;

    gemm16_main(sb, t, A, W, m0, n0, c);

#pragma unroll
    for (int mi = 0; mi < 4; mi++) {
        const int r0 = m0 + wm * 64 + mi * 16 + (lane >> 2);
#pragma unroll
        for (int ni = 0; ni < 4; ni++) {
            const int col = n0 + wn * 32 + ni * 8 + (lane & 3) * 2;
            const float b0 = bias[col], b1 = bias[col + 1];
            *(float2*)(Cf + (size_t)r0 * D_MODEL + col) =
                make_float2(c[mi][ni][0] + b0, c[mi][ni][1] + b1);
            *(float2*)(Cf + (size_t)(r0 + 8) * D_MODEL + col) =
                make_float2(c[mi][ni][2] + b0, c[mi][ni][3] + b1);
        }
    }
}

// ============================================================================
// FA2 attention — EXACT R12 structure (known 220.7 us):
// 256 threads / 8 warps / 128 q-rows, 2 CTAs/SM, exp2-domain softmax,
// per-iteration warp-local l reduction.
// ============================================================================
#define AST 144
#define AT_Q  0
#define AT_K(b) (AT_Q + 128 * AST + (b) * (128 * AST))
#define AT_V(b) (AT_Q + 128 * AST + 2 * (128 * AST) + (b) * (128 * AST))
#define ATTN_SMEM (128 * AST + 4 * (128 * AST))   /* 92160 B */

__global__ __launch_bounds__(256, 2) void attn_tc()
{
    extern __shared__ char smem[];
    const uint32_t sb = smem_u32(smem);
    const int t = threadIdx.x;
    const int lane = t & 31, w = t >> 5;
    const int qt = blockIdx.x, bh = blockIdx.y;

    const __half* Qs = g_Q16 + ((size_t)bh * SEQ + qt * 128) * DK;
    const __half* Kg = g_K16 + (size_t)bh * SEQ * DK;
    const __half* Vg = g_V16 + (size_t)bh * SEQ * DK;

    auto ldtile = [&](uint32_t dstoff, const __half* src) {   // 128x64 fp16
#pragma unroll
        for (int j = 0; j < 4; j++) {
            int idx = t + j * 256;
            int r = idx >> 3, cc = idx & 7;
            CP_ASYNC16(sb + dstoff + r * AST + cc * 16, src + r * DK + cc * 8);
        }
    };

    ldtile(AT_Q, Qs);
    ldtile(AT_K(0), Kg);
    ldtile(AT_V(0), Vg);
    CP_ASYNC_COMMIT();
    CP_ASYNC_WAIT_ALL();
    __syncthreads();

    float o[8][4];
#pragma unroll
    for (int i = 0; i < 8; i++)
#pragma unroll
        for (int k = 0; k < 4; k++) o[i][k] = 0.0f;
    float m0 = -1e30f, m1 = -1e30f, l0 = 0.0f, l1 = 0.0f;

    for (int kt = 0; kt < KVTILES; kt++) {
        const int vb = kt & 1;

        if (kt + 1 < KVTILES) {
            ldtile(AT_K(vb ^ 1), Kg + (size_t)(kt + 1) * 128 * DK);
            ldtile(AT_V(vb ^ 1), Vg + (size_t)(kt + 1) * 128 * DK);
            CP_ASYNC_COMMIT();
        }

        // ---- S' = Q' K^T  (log2 units) ----
        float c[16][4];
#pragma unroll
        for (int i = 0; i < 16; i++)
#pragma unroll
            for (int k = 0; k < 4; k++) c[i][k] = 0.0f;

#pragma unroll
        for (int kk = 0; kk < 4; kk++) {
            uint32_t q[4];
            {
                uint32_t ro = (uint32_t)((w * 16 + (lane & 15)) * AST
                                         + (kk * 16 + (lane >> 4) * 8) * 2);
                ldsm4(q, sb + AT_Q + ro);
            }
#pragma unroll
            for (int nj = 0; nj < 8; nj++) {
                uint32_t bk_[4];
                uint32_t ro = (uint32_t)((nj * 16 + (lane & 7) + ((lane >> 4) * 8)) * AST
                                         + (kk * 16 + ((lane >> 3) & 1) * 8) * 2);
                ldsm4(bk_, sb + AT_K(vb) + ro);
                mma_f16(c[2 * nj],     q, bk_[0], bk_[1]);
                mma_f16(c[2 * nj + 1], q, bk_[2], bk_[3]);
            }
        }

        // ---- warp-local online softmax (exp2 domain) ----
        float mx0 = -1e30f, mx1 = -1e30f;
#pragma unroll
        for (int ni = 0; ni < 16; ni++) {
            mx0 = fmaxf(mx0, fmaxf(c[ni][0], c[ni][1]));
            mx1 = fmaxf(mx1, fmaxf(c[ni][2], c[ni][3]));
        }
        mx0 = fmaxf(mx0, __shfl_xor_sync(0xffffffffu, mx0, 1));
        mx0 = fmaxf(mx0, __shfl_xor_sync(0xffffffffu, mx0, 2));
        mx1 = fmaxf(mx1, __shfl_xor_sync(0xffffffffu, mx1, 1));
        mx1 = fmaxf(mx1, __shfl_xor_sync(0xffffffffu, mx1, 2));

        const float nm0 = fmaxf(m0, mx0), nm1 = fmaxf(m1, mx1);
        const float alpha0 = exp2f(m0 - nm0), alpha1 = exp2f(m1 - nm1);
        m0 = nm0; m1 = nm1;

        float s0 = 0.0f, s1 = 0.0f;
#pragma unroll
        for (int ni = 0; ni < 16; ni++) {
            c[ni][0] = exp2f(c[ni][0] - nm0);
            c[ni][1] = exp2f(c[ni][1] - nm0);
            c[ni][2] = exp2f(c[ni][2] - nm1);
            c[ni][3] = exp2f(c[ni][3] - nm1);
            s0 += c[ni][0] + c[ni][1];
            s1 += c[ni][2] + c[ni][3];
        }
        s0 += __shfl_xor_sync(0xffffffffu, s0, 1);
        s0 += __shfl_xor_sync(0xffffffffu, s0, 2);
        s1 += __shfl_xor_sync(0xffffffffu, s1, 1);
        s1 += __shfl_xor_sync(0xffffffffu, s1, 2);
        l0 = l0 * alpha0 + s0;
        l1 = l1 * alpha1 + s1;

#pragma unroll
        for (int i = 0; i < 8; i++) {
            o[i][0] *= alpha0; o[i][1] *= alpha0;
            o[i][2] *= alpha1; o[i][3] *= alpha1;
        }

        // ---- O += P V ----
#pragma unroll
        for (int kk = 0; kk < 8; kk++) {
            uint32_t ph[4];
            ph[0] = pack_h16(c[2 * kk][0], c[2 * kk][1]);
            ph[1] = pack_h16(c[2 * kk][2], c[2 * kk][3]);
            ph[2] = pack_h16(c[2 * kk + 1][0], c[2 * kk + 1][1]);
            ph[3] = pack_h16(c[2 * kk + 1][2], c[2 * kk + 1][3]);
#pragma unroll
            for (int nj = 0; nj < 4; nj++) {
                uint32_t vh[4];
                uint32_t ro = (uint32_t)((kk * 16 + (lane & 15)) * AST
                                         + (nj * 16 + (lane >> 4) * 8) * 2);
                ldsm4t(vh, sb + AT_V(vb) + ro);
                mma_f16(o[2 * nj],     ph, vh[0], vh[1]);
                mma_f16(o[2 * nj + 1], ph, vh[2], vh[3]);
            }
        }

        if (kt + 1 < KVTILES) CP_ASYNC_WAIT_ALL();
        __syncthreads();
    }

    // ---- epilogue ----
    const int b = bh >> 4, h = bh & 15;
    const float inv0 = 1.0f / l0, inv1 = 1.0f / l1;
    const size_t row0 = (size_t)(b * SEQ + qt * 128 + w * 16 + (lane >> 2));
#pragma unroll
    for (int on = 0; on < 8; on++) {
        const int colg = h * DK + on * 8 + (lane & 3) * 2;
        *(uint32_t*)(g_ctx16 + row0 * D_MODEL + colg) = pack_h16(o[on][0] * inv0, o[on][1] * inv0);
        *(uint32_t*)(g_ctx16 + (row0 + 8) * D_MODEL + colg) = pack_h16(o[on][2] * inv1, o[on][3] * inv1);
    }
}

// ============================================================================
// launch
// ============================================================================
extern "C" void kernel_launch(void* const* d_in, const int* in_sizes, int n_in,
                              void* d_out, int out_size)
{
    const float* query  = (const float*)d_in[0];
    const float* key_in = (const float*)d_in[1];
    const float* value  = (const float*)d_in[2];
    const float* Wq = (const float*)d_in[3];
    const float* bq = (const float*)d_in[4];
    const float* Wk = (const float*)d_in[5];
    const float* bk = (const float*)d_in[6];
    const float* Wv = (const float*)d_in[7];
    const float* bv = (const float*)d_in[8];
    const float* Wo = (const float*)d_in[9];
    const float* bo = (const float*)d_in[10];
    float* out = (float*)d_out;

    __half *q16, *k16, *v16, *ctx16, *a16, *w16;
    cudaGetSymbolAddress((void**)&q16, g_Q16);
    cudaGetSymbolAddress((void**)&k16, g_K16);
    cudaGetSymbolAddress((void**)&v16, g_V16);
    cudaGetSymbolAddress((void**)&ctx16, g_ctx16);
    cudaGetSymbolAddress((void**)&a16, g_a16);
    cudaGetSymbolAddress((void**)&w16, g_w16);

    cudaFuncSetAttribute(gemm_qkv16, cudaFuncAttributeMaxDynamicSharedMemorySize, GEMM16_SMEM);
    cudaFuncSetAttribute(gemm_out16, cudaFuncAttributeMaxDynamicSharedMemorySize, GEMM16_SMEM);
    cudaFuncSetAttribute(attn_tc, cudaFuncAttributeMaxDynamicSharedMemorySize, ATTN_SMEM);

    const int ACT4 = MROWS * D_MODEL / 4;
    const int W4   = D_MODEL * D_MODEL / 4;
    const size_t WSL = (size_t)D_MODEL * D_MODEL;

    // conversions: 4 float4 per thread (MLP=4)
    conv_w4<<<dim3((W4 / 4 + 255) / 256, 4), 256>>>(Wq, Wk, Wv, Wo, w16, W4);
    conv_a3<<<dim3((ACT4 / 4 + 255) / 256, 3), 256>>>(query, key_in, value, a16, ACT4);

    gemm_qkv16<<<dim3(D_MODEL / 128, MROWS / 128, 3), 256, GEMM16_SMEM>>>(
        a16, w16, bq, bk, bv, q16, k16, v16);

    attn_tc<<<dim3(SEQ / 128, BATCH * NUM_HEADS), dim3(256), ATTN_SMEM>>>();

    gemm_out16<<<dim3(D_MODEL / 128, MROWS / 128), 256, GEMM16_SMEM>>>(
        ctx16, w16 + 3 * WSL, bo, out);
}

// round 16
// speedup vs baseline: 1.0519x; 1.0078x over previous
#include <cuda_runtime.h>
#include <cuda_fp16.h>
#include <cstdint>

#define D_MODEL 1024
#define NUM_HEADS 16
#define DK 64
#define BATCH 4
#define SEQ 2048
#define MROWS (BATCH * SEQ)   /* 8192 */
#define KVTILES (SEQ / 128)   /* 16 */

// ---------------- scratch (all single fp16) ----------------
__device__ __half g_Q16[BATCH * NUM_HEADS * SEQ * DK];
__device__ __half g_K16[BATCH * NUM_HEADS * SEQ * DK];
__device__ __half g_V16[BATCH * NUM_HEADS * SEQ * DK];
__device__ __half g_ctx16[MROWS * D_MODEL];
__device__ __half g_a16[3 * MROWS * D_MODEL];     // query,key,value acts
__device__ __half g_w16[4 * D_MODEL * D_MODEL];   // Wq,Wk,Wv,Wo

// ---------------- helpers ----------------
__device__ __forceinline__ uint32_t smem_u32(const void* p) {
    uint32_t a;
    asm("{ .reg .u64 t; cvta.to.shared.u64 t, %1; cvt.u32.u64 %0, t; }" : "=r"(a) : "l"(p));
    return a;
}
#define CP_ASYNC16(saddr, gptr) \
    asm volatile("cp.async.cg.shared.global [%0], [%1], 16;" :: "r"((uint32_t)(saddr)), "l"(gptr))
#define CP_ASYNC_COMMIT()    asm volatile("cp.async.commit_group;" ::: "memory")
#define CP_ASYNC_WAIT_ALL()  asm volatile("cp.async.wait_group 0;" ::: "memory")
#define CP_ASYNC_WAIT_1()    asm volatile("cp.async.wait_group 1;" ::: "memory")

__device__ __forceinline__ void ldsm4(uint32_t r[4], uint32_t a) {
    asm volatile("ldmatrix.sync.aligned.m8n8.x4.shared.b16 {%0,%1,%2,%3}, [%4];"
        : "=r"(r[0]), "=r"(r[1]), "=r"(r[2]), "=r"(r[3]) : "r"(a));
}
__device__ __forceinline__ void ldsm4t(uint32_t r[4], uint32_t a) {
    asm volatile("ldmatrix.sync.aligned.m8n8.x4.trans.shared.b16 {%0,%1,%2,%3}, [%4];"
        : "=r"(r[0]), "=r"(r[1]), "=r"(r[2]), "=r"(r[3]) : "r"(a));
}
__device__ __forceinline__ void mma_f16(float c[4], const uint32_t a[4], uint32_t b0, uint32_t b1) {
    asm volatile("mma.sync.aligned.m16n8k16.row.col.f32.f16.f16.f32 "
        "{%0,%1,%2,%3}, {%4,%5,%6,%7}, {%8,%9}, {%0,%1,%2,%3};"
        : "+f"(c[0]), "+f"(c[1]), "+f"(c[2]), "+f"(c[3])
        : "r"(a[0]), "r"(a[1]), "r"(a[2]), "r"(a[3]), "r"(b0), "r"(b1));
}
__device__ __forceinline__ uint32_t pack_h16(float x, float y) {
    __half2 h = __floats2half2_rn(x, y);
    return *(uint32_t*)&h;
}

// ============================================================================
// single fused conversion: flat grid, zero idle blocks.
// blocks [0, 1024): weights (256 blocks per tensor, W4/4 = 65536 threads each)
// blocks [1024, 7168): activations (2048 blocks per tensor)
// each thread converts 4 float4 (MLP=4). Bit-identical math to R15.
// ============================================================================
#define W4   (D_MODEL * D_MODEL / 4)       /* 262144 float4 */
#define ACT4 (MROWS * D_MODEL / 4)         /* 2097152 float4 */
#define WBLK ((W4 / 4) / 256)              /* 256 blocks per weight tensor */
#define ABLK ((ACT4 / 4) / 256)            /* 2048 blocks per activation */

__global__ __launch_bounds__(256) void conv_all(
    const float* __restrict__ w0, const float* __restrict__ w1,
    const float* __restrict__ w2, const float* __restrict__ w3,
    const float* __restrict__ a0, const float* __restrict__ a1,
    const float* __restrict__ a2,
    __half* __restrict__ w16, __half* __restrict__ a16)
{
    const int bid = blockIdx.x;
    const float* x;
    __half* dst;
    int i0;
    if (bid < 4 * WBLK) {
        const int z = bid / WBLK;
        const int local = bid - z * WBLK;
        x = (z == 0) ? w0 : (z == 1) ? w1 : (z == 2) ? w2 : w3;
        dst = w16 + (size_t)z * D_MODEL * D_MODEL;
        i0 = (local * 256 + threadIdx.x) * 4;
    } else {
        const int b2 = bid - 4 * WBLK;
        const int z = b2 / ABLK;
        const int local = b2 - z * ABLK;
        x = (z == 0) ? a0 : (z == 1) ? a1 : a2;
        dst = a16 + (size_t)z * MROWS * D_MODEL;
        i0 = (local * 256 + threadIdx.x) * 4;
    }
    float4 v0 = ((const float4*)x)[i0 + 0];
    float4 v1 = ((const float4*)x)[i0 + 1];
    float4 v2 = ((const float4*)x)[i0 + 2];
    float4 v3 = ((const float4*)x)[i0 + 3];
    uint4 H0, H1;
    H0.x = pack_h16(v0.x, v0.y); H0.y = pack_h16(v0.z, v0.w);
    H0.z = pack_h16(v1.x, v1.y); H0.w = pack_h16(v1.z, v1.w);
    H1.x = pack_h16(v2.x, v2.y); H1.y = pack_h16(v2.z, v2.w);
    H1.z = pack_h16(v3.x, v3.y); H1.w = pack_h16(v3.z, v3.w);
    uint2* d2 = (uint2*)dst + i0;
    *(uint4*)(d2 + 0) = H0;
    *(uint4*)(d2 + 2) = H1;
}

// ============================================================================
// fp16 1-term GEMM. BM=BN=128, BK=64, 8 warps, 3-stage cp.async pipeline.
// (unchanged from R15)
// ============================================================================
#define BK 64
#define GST 144
#define MAT16 (128 * GST)
#define STG16 (2 * MAT16)
#define NIT (D_MODEL / BK)
#define NSTG 3
#define GEMM16_SMEM (NSTG * STG16)

__device__ __forceinline__ void gemm16_main(
    uint32_t sb, int t,
    const __half* __restrict__ A, const __half* __restrict__ W,
    int m0, int n0, float c[4][4][4])
{
    const int lane = t & 31, wid = t >> 5;
    const int wm = wid >> 2, wn = wid & 3;

    auto load_stage = [&](int s, int it) {
        const int k0 = it * BK;
        const uint32_t st = sb + s * STG16;
#pragma unroll
        for (int j = 0; j < 4; j++) {
            int idx = t + j * 256;
            int r = idx >> 3, cc = idx & 7;
            uint32_t so = (uint32_t)(r * GST + cc * 16);
            CP_ASYNC16(st + 0 * MAT16 + so, A + (size_t)(m0 + r) * D_MODEL + k0 + cc * 8);
            CP_ASYNC16(st + 1 * MAT16 + so, W + (size_t)(n0 + r) * D_MODEL + k0 + cc * 8);
        }
    };

    load_stage(0, 0);
    CP_ASYNC_COMMIT();
    load_stage(1, 1);
    CP_ASYNC_COMMIT();

    for (int it = 0; it < NIT; ++it) {
        const int s = it % NSTG;
        CP_ASYNC_WAIT_1();
        __syncthreads();
        if (it + 2 < NIT) {
            load_stage((it + 2) % NSTG, it + 2);
            CP_ASYNC_COMMIT();
        }
        const uint32_t st = sb + s * STG16;
#pragma unroll
        for (int kk = 0; kk < 4; kk++) {
            uint32_t ah[4][4];
#pragma unroll
            for (int mi = 0; mi < 4; mi++) {
                uint32_t ro = (uint32_t)((wm * 64 + mi * 16 + (lane & 15)) * GST
                                         + (kk * 16 + (lane >> 4) * 8) * 2);
                ldsm4(ah[mi], st + 0 * MAT16 + ro);
            }
            uint32_t bh_[2][4];
#pragma unroll
            for (int nj = 0; nj < 2; nj++) {
                uint32_t ro = (uint32_t)((wn * 32 + nj * 16 + (lane & 7) + ((lane >> 4) * 8)) * GST
                                         + (kk * 16 + ((lane >> 3) & 1) * 8) * 2);
                ldsm4(bh_[nj], st + 1 * MAT16 + ro);
            }
#pragma unroll
            for (int mi = 0; mi < 4; mi++)
#pragma unroll
                for (int ni = 0; ni < 4; ni++) {
                    const int nj = ni >> 1, ss = (ni & 1) * 2;
                    mma_f16(c[mi][ni], ah[mi], bh_[nj][ss], bh_[nj][ss + 1]);
                }
        }
    }
}

// ---- fused Q/K/V projections (Q scaled by 0.125*log2e for exp2 softmax) ----
__global__ __launch_bounds__(256, 2) void gemm_qkv16(
    const __half* __restrict__ a16, const __half* __restrict__ w16,
    const float* __restrict__ bq, const float* __restrict__ bk,
    const float* __restrict__ bv,
    __half* __restrict__ q16, __half* __restrict__ k16, __half* __restrict__ v16)
{
    extern __shared__ char smem[];
    const uint32_t sb = smem_u32(smem);
    const int t = threadIdx.x;
    const int lane = t & 31, wid = t >> 5;
    const int wm = wid >> 2, wn = wid & 3;
    const int m0 = blockIdx.y * 128, n0 = blockIdx.x * 128;
    const int z = blockIdx.z;

    const __half* A = a16 + (size_t)z * MROWS * D_MODEL;
    const __half* W = w16 + (size_t)z * D_MODEL * D_MODEL;
    const float* bias = (z == 0) ? bq : (z == 1) ? bk : bv;
    __half* C = (z == 0) ? q16 : (z == 1) ? k16 : v16;
    const float oscale = (z == 0) ? 0.125f * 1.44269504088896f : 1.0f;

    float c[4][4][4];
#pragma unroll
    for (int i = 0; i < 4; i++)
#pragma unroll
        for (int j = 0; j < 4; j++)
#pragma unroll
            for (int k = 0; k < 4; k++) c[i][j][k] = 0.0f;

    gemm16_main(sb, t, A, W, m0, n0, c);

#pragma unroll
    for (int mi = 0; mi < 4; mi++) {
        const int r0 = m0 + wm * 64 + mi * 16 + (lane >> 2);
#pragma unroll
        for (int ni = 0; ni < 4; ni++) {
            const int col = n0 + wn * 32 + ni * 8 + (lane & 3) * 2;
            const float b0 = bias[col], b1 = bias[col + 1];
            const int h = col >> 6, d = col & 63;
            float v00 = (c[mi][ni][0] + b0) * oscale, v01 = (c[mi][ni][1] + b1) * oscale;
            float v10 = (c[mi][ni][2] + b0) * oscale, v11 = (c[mi][ni][3] + b1) * oscale;
#pragma unroll
            for (int rr = 0; rr < 2; rr++) {
                const int m = r0 + rr * 8;
                const int b = m >> 11, sdx = m & 2047;
                const size_t off = (((size_t)(b * NUM_HEADS + h) * SEQ + sdx) * DK + d);
                *(uint32_t*)(C + off) = pack_h16(rr ? v10 : v00, rr ? v11 : v01);
            }
        }
    }
}

// ---- output projection: fp32 row-major out ----
__global__ __launch_bounds__(256, 2) void gemm_out16(
    const __half* __restrict__ A, const __half* __restrict__ W,
    const float* __restrict__ bias, float* __restrict__ Cf)
{
    extern __shared__ char smem[];
    const uint32_t sb = smem_u32(smem);
    const int t = threadIdx.x;
    const int lane = t & 31, wid = t >> 5;
    const int wm = wid >> 2, wn = wid & 3;
    const int m0 = blockIdx.y * 128, n0 = blockIdx.x * 128;

    float c[4][4][4];
#pragma unroll
    for (int i = 0; i < 4; i++)
#pragma unroll
        for (int j = 0; j < 4; j++)
#pragma unroll
            for (int k = 0; k < 4; k++) c[i][j][k] = 0.0f;

    gemm16_main(sb, t, A, W, m0, n0, c);

#pragma unroll
    for (int mi = 0; mi < 4; mi++) {
        const int r0 = m0 + wm * 64 + mi * 16 + (lane >> 2);
#pragma unroll
        for (int ni = 0; ni < 4; ni++) {
            const int col = n0 + wn * 32 + ni * 8 + (lane & 3) * 2;
            const float b0 = bias[col], b1 = bias[col + 1];
            *(float2*)(Cf + (size_t)r0 * D_MODEL + col) =
                make_float2(c[mi][ni][0] + b0, c[mi][ni][1] + b1);
            *(float2*)(Cf + (size_t)(r0 + 8) * D_MODEL + col) =
                make_float2(c[mi][ni][2] + b0, c[mi][ni][3] + b1);
        }
    }
}

// ============================================================================
// FA2 attention — EXACT R12/R15 structure (known 221.5 us):
// 256 threads / 8 warps / 128 q-rows, 2 CTAs/SM, exp2-domain softmax,
// per-iteration warp-local l reduction.
// ============================================================================
#define AST 144
#define AT_Q  0
#define AT_K(b) (AT_Q + 128 * AST + (b) * (128 * AST))
#define AT_V(b) (AT_Q + 128 * AST + 2 * (128 * AST) + (b) * (128 * AST))
#define ATTN_SMEM (128 * AST + 4 * (128 * AST))   /* 92160 B */

__global__ __launch_bounds__(256, 2) void attn_tc()
{
    extern __shared__ char smem[];
    const uint32_t sb = smem_u32(smem);
    const int t = threadIdx.x;
    const int lane = t & 31, w = t >> 5;
    const int qt = blockIdx.x, bh = blockIdx.y;

    const __half* Qs = g_Q16 + ((size_t)bh * SEQ + qt * 128) * DK;
    const __half* Kg = g_K16 + (size_t)bh * SEQ * DK;
    const __half* Vg = g_V16 + (size_t)bh * SEQ * DK;

    auto ldtile = [&](uint32_t dstoff, const __half* src) {   // 128x64 fp16
#pragma unroll
        for (int j = 0; j < 4; j++) {
            int idx = t + j * 256;
            int r = idx >> 3, cc = idx & 7;
            CP_ASYNC16(sb + dstoff + r * AST + cc * 16, src + r * DK + cc * 8);
        }
    };

    ldtile(AT_Q, Qs);
    ldtile(AT_K(0), Kg);
    ldtile(AT_V(0), Vg);
    CP_ASYNC_COMMIT();
    CP_ASYNC_WAIT_ALL();
    __syncthreads();

    float o[8][4];
#pragma unroll
    for (int i = 0; i < 8; i++)
#pragma unroll
        for (int k = 0; k < 4; k++) o[i][k] = 0.0f;
    float m0 = -1e30f, m1 = -1e30f, l0 = 0.0f, l1 = 0.0f;

    for (int kt = 0; kt < KVTILES; kt++) {
        const int vb = kt & 1;

        if (kt + 1 < KVTILES) {
            ldtile(AT_K(vb ^ 1), Kg + (size_t)(kt + 1) * 128 * DK);
            ldtile(AT_V(vb ^ 1), Vg + (size_t)(kt + 1) * 128 * DK);
            CP_ASYNC_COMMIT();
        }

        // ---- S' = Q' K^T  (log2 units) ----
        float c[16][4];
#pragma unroll
        for (int i = 0; i < 16; i++)
#pragma unroll
            for (int k = 0; k < 4; k++) c[i][k] = 0.0f;

#pragma unroll
        for (int kk = 0; kk < 4; kk++) {
            uint32_t q[4];
            {
                uint32_t ro = (uint32_t)((w * 16 + (lane & 15)) * AST
                                         + (kk * 16 + (lane >> 4) * 8) * 2);
                ldsm4(q, sb + AT_Q + ro);
            }
#pragma unroll
            for (int nj = 0; nj < 8; nj++) {
                uint32_t bk_[4];
                uint32_t ro = (uint32_t)((nj * 16 + (lane & 7) + ((lane >> 4) * 8)) * AST
                                         + (kk * 16 + ((lane >> 3) & 1) * 8) * 2);
                ldsm4(bk_, sb + AT_K(vb) + ro);
                mma_f16(c[2 * nj],     q, bk_[0], bk_[1]);
                mma_f16(c[2 * nj + 1], q, bk_[2], bk_[3]);
            }
        }

        // ---- warp-local online softmax (exp2 domain) ----
        float mx0 = -1e30f, mx1 = -1e30f;
#pragma unroll
        for (int ni = 0; ni < 16; ni++) {
            mx0 = fmaxf(mx0, fmaxf(c[ni][0], c[ni][1]));
            mx1 = fmaxf(mx1, fmaxf(c[ni][2], c[ni][3]));
        }
        mx0 = fmaxf(mx0, __shfl_xor_sync(0xffffffffu, mx0, 1));
        mx0 = fmaxf(mx0, __shfl_xor_sync(0xffffffffu, mx0, 2));
        mx1 = fmaxf(mx1, __shfl_xor_sync(0xffffffffu, mx1, 1));
        mx1 = fmaxf(mx1, __shfl_xor_sync(0xffffffffu, mx1, 2));

        const float nm0 = fmaxf(m0, mx0), nm1 = fmaxf(m1, mx1);
        const float alpha0 = exp2f(m0 - nm0), alpha1 = exp2f(m1 - nm1);
        m0 = nm0; m1 = nm1;

        float s0 = 0.0f, s1 = 0.0f;
#pragma unroll
        for (int ni = 0; ni < 16; ni++) {
            c[ni][0] = exp2f(c[ni][0] - nm0);
            c[ni][1] = exp2f(c[ni][1] - nm0);
            c[ni][2] = exp2f(c[ni][2] - nm1);
            c[ni][3] = exp2f(c[ni][3] - nm1);
            s0 += c[ni][0] + c[ni][1];
            s1 += c[ni][2] + c[ni][3];
        }
        s0 += __shfl_xor_sync(0xffffffffu, s0, 1);
        s0 += __shfl_xor_sync(0xffffffffu, s0, 2);
        s1 += __shfl_xor_sync(0xffffffffu, s1, 1);
        s1 += __shfl_xor_sync(0xffffffffu, s1, 2);
        l0 = l0 * alpha0 + s0;
        l1 = l1 * alpha1 + s1;

#pragma unroll
        for (int i = 0; i < 8; i++) {
            o[i][0] *= alpha0; o[i][1] *= alpha0;
            o[i][2] *= alpha1; o[i][3] *= alpha1;
        }

        // ---- O += P V ----
#pragma unroll
        for (int kk = 0; kk < 8; kk++) {
            uint32_t ph[4];
            ph[0] = pack_h16(c[2 * kk][0], c[2 * kk][1]);
            ph[1] = pack_h16(c[2 * kk][2], c[2 * kk][3]);
            ph[2] = pack_h16(c[2 * kk + 1][0], c[2 * kk + 1][1]);
            ph[3] = pack_h16(c[2 * kk + 1][2], c[2 * kk + 1][3]);
#pragma unroll
            for (int nj = 0; nj < 4; nj++) {
                uint32_t vh[4];
                uint32_t ro = (uint32_t)((kk * 16 + (lane & 15)) * AST
                                         + (nj * 16 + (lane >> 4) * 8) * 2);
                ldsm4t(vh, sb + AT_V(vb) + ro);
                mma_f16(o[2 * nj],     ph, vh[0], vh[1]);
                mma_f16(o[2 * nj + 1], ph, vh[2], vh[3]);
            }
        }

        if (kt + 1 < KVTILES) CP_ASYNC_WAIT_ALL();
        __syncthreads();
    }

    // ---- epilogue ----
    const int b = bh >> 4, h = bh & 15;
    const float inv0 = 1.0f / l0, inv1 = 1.0f / l1;
    const size_t row0 = (size_t)(b * SEQ + qt * 128 + w * 16 + (lane >> 2));
#pragma unroll
    for (int on = 0; on < 8; on++) {
        const int colg = h * DK + on * 8 + (lane & 3) * 2;
        *(uint32_t*)(g_ctx16 + row0 * D_MODEL + colg) = pack_h16(o[on][0] * inv0, o[on][1] * inv0);
        *(uint32_t*)(g_ctx16 + (row0 + 8) * D_MODEL + colg) = pack_h16(o[on][2] * inv1, o[on][3] * inv1);
    }
}

// ============================================================================
// launch
// ============================================================================
extern "C" void kernel_launch(void* const* d_in, const int* in_sizes, int n_in,
                              void* d_out, int out_size)
{
    const float* query  = (const float*)d_in[0];
    const float* key_in = (const float*)d_in[1];
    const float* value  = (const float*)d_in[2];
    const float* Wq = (const float*)d_in[3];
    const float* bq = (const float*)d_in[4];
    const float* Wk = (const float*)d_in[5];
    const float* bk = (const float*)d_in[6];
    const float* Wv = (const float*)d_in[7];
    const float* bv = (const float*)d_in[8];
    const float* Wo = (const float*)d_in[9];
    const float* bo = (const float*)d_in[10];
    float* out = (float*)d_out;

    __half *q16, *k16, *v16, *ctx16, *a16, *w16;
    cudaGetSymbolAddress((void**)&q16, g_Q16);
    cudaGetSymbolAddress((void**)&k16, g_K16);
    cudaGetSymbolAddress((void**)&v16, g_V16);
    cudaGetSymbolAddress((void**)&ctx16, g_ctx16);
    cudaGetSymbolAddress((void**)&a16, g_a16);
    cudaGetSymbolAddress((void**)&w16, g_w16);

    cudaFuncSetAttribute(gemm_qkv16, cudaFuncAttributeMaxDynamicSharedMemorySize, GEMM16_SMEM);
    cudaFuncSetAttribute(gemm_out16, cudaFuncAttributeMaxDynamicSharedMemorySize, GEMM16_SMEM);
    cudaFuncSetAttribute(attn_tc, cudaFuncAttributeMaxDynamicSharedMemorySize, ATTN_SMEM);

    const size_t WSL = (size_t)D_MODEL * D_MODEL;

    // single fused conversion launch: 4*WBLK + 3*ABLK blocks, zero idle
    conv_all<<<4 * WBLK + 3 * ABLK, 256>>>(
        Wq, Wk, Wv, Wo, query, key_in, value, w16, a16);

    gemm_qkv16<<<dim3(D_MODEL / 128, MROWS / 128, 3), 256, GEMM16_SMEM>>>(
        a16, w16, bq, bk, bv, q16, k16, v16);

    attn_tc<<<dim3(SEQ / 128, BATCH * NUM_HEADS), dim3(256), ATTN_SMEM>>>();

    gemm_out16<<<dim3(D_MODEL / 128, MROWS / 128), 256, GEMM16_SMEM>>>(
        ctx16, w16 + 3 * WSL, bo, out);
}